// round 12
// baseline (speedup 1.0000x reference)
#include <cuda_runtime.h>
#include <cuda_bf16.h>

#define BATCH 8
#define NPTS  32768
#define NCH   96
#define NSAMP 1024
#define CSZ   8                 // CTAs per batch (cluster)
#define NL    (NPTS / CSZ)      // 4096 points per CTA  (idx>>12 == rank)
#define T     256
#define PPT   (NL / T)          // 16 points per thread
#define NPAIR (PPT / 2)         // 8 packed pairs
#define NWARP (T / 32)          // 8 warps
#define NSLOT (CSZ * NWARP)     // 64 mailbox slots per parity
#define SLOTB 24                // slot bytes: {d,x | y,z | idx,tag}

// Scratch (no device allocation allowed).
__device__ int g_idx[BATCH * NSAMP];

// ---------------- packed f32x2 helpers (per-lane IEEE rn => bit-exact) -----
typedef unsigned long long ull;
__device__ __forceinline__ ull pk(float a, float b) {
    ull r; asm("mov.b64 %0, {%1,%2};" : "=l"(r) : "f"(a), "f"(b)); return r;
}
__device__ __forceinline__ void upk(ull v, float& a, float& b) {
    asm("mov.b64 {%0,%1}, %2;" : "=f"(a), "=f"(b) : "l"(v));
}
__device__ __forceinline__ ull addx2(ull a, ull b) {
    ull r; asm("add.rn.f32x2 %0, %1, %2;" : "=l"(r) : "l"(a), "l"(b)); return r;
}
__device__ __forceinline__ ull mulx2(ull a, ull b) {
    ull r; asm("mul.rn.f32x2 %0, %1, %2;" : "=l"(r) : "l"(a), "l"(b)); return r;
}
__device__ __forceinline__ unsigned su32(const void* p) {
    unsigned r;
    asm("{.reg .u64 t; cvta.to.shared.u64 t, %1; cvt.u32.u64 %0, t;}" : "=r"(r) : "l"(p));
    return r;
}

// ---------------------------------------------------------------------------
// FPS: 8-CTA cluster per batch, 8 fully autonomous warps per CTA. Each warp
// scans its 512 points (packed f32x2), warp-redux argmax, then pushes its OWN
// {d,x,y,z,idx,tag} slot to all 8 peer CTAs (warp-level all-to-all; no
// __syncthreads, no CTA funnel). Consumers spin on all 64 tags and redux over
// the 64 candidates (max dist, tie -> min index at every level).
// ---------------------------------------------------------------------------
__global__ void __cluster_dims__(CSZ, 1, 1) __launch_bounds__(T, 1)
fps_kernel(const float* __restrict__ xyz,
           float* __restrict__ out_xyz,
           float* __restrict__ out_idxf)
{
    extern __shared__ float smem[];
    float*    sx = smem;                          // winner-coord lookup copies
    float*    sy = smem + NL;
    float*    sz = smem + 2 * NL;
    unsigned* mb = (unsigned*)(smem + 3 * NL);    // [2][NSLOT] slots of 6 u32

    const int rank = blockIdx.x;
    const int b    = blockIdx.y;
    const int tid  = threadIdx.x;
    const int lane = tid & 31;
    const int warp = tid >> 5;
    const int base = rank * NL;
    const float* __restrict__ p = xyz + (size_t)b * NPTS * 3;

    // ---- one-time: load my 16 points -> packed registers + smem lookup copy
    ull x2[NPAIR], y2[NPAIR], z2[NPAIR];
    {
        float buf[48];
        const float4* p4 = (const float4*)(p + (size_t)(base + tid * PPT) * 3);
#pragma unroll
        for (int k = 0; k < 12; k++) ((float4*)buf)[k] = p4[k];
#pragma unroll
        for (int i = 0; i < PPT; i++) {
            sx[tid * PPT + i] = buf[3 * i];
            sy[tid * PPT + i] = buf[3 * i + 1];
            sz[tid * PPT + i] = buf[3 * i + 2];
        }
#pragma unroll
        for (int q = 0; q < NPAIR; q++) {
            x2[q] = pk(buf[6 * q + 0], buf[6 * q + 3]);
            y2[q] = pk(buf[6 * q + 1], buf[6 * q + 4]);
            z2[q] = pk(buf[6 * q + 2], buf[6 * q + 5]);
        }
    }

    // ---- init mailbox tags (word 5 of each slot), then one cluster barrier
    if (tid < 2 * NSLOT) mb[tid * 6 + 5] = 0xFFFFFFFFu;
    __syncthreads();
    asm volatile("barrier.cluster.arrive.aligned;\n" ::: "memory");
    asm volatile("barrier.cluster.wait.aligned;\n"   ::: "memory");

    const unsigned mb_u = su32(mb);

    // Remote slot addresses: EVERY warp's lanes 0..7 push this warp's slot
    // [parity][rank*NWARP + warp] into peer CTA 'lane'.
    unsigned rem0 = 0, rem1 = 0;
    if (lane < CSZ) {
        const int slot = rank * NWARP + warp;
        const unsigned l0 = mb_u + (unsigned)((0 * NSLOT + slot) * SLOTB);
        const unsigned l1 = mb_u + (unsigned)((1 * NSLOT + slot) * SLOTB);
        asm("mapa.shared::cluster.u32 %0, %1, %2;" : "=r"(rem0) : "r"(l0), "r"(lane));
        asm("mapa.shared::cluster.u32 %0, %1, %2;" : "=r"(rem1) : "r"(l1), "r"(lane));
    }

    float dist[PPT];
#pragma unroll
    for (int i = 0; i < PPT; i++) dist[i] = 1e10f;

    int   cur = 0;
    float cx = __ldg(p + 0), cy = __ldg(p + 1), cz = __ldg(p + 2);

    for (int s = 0; s < NSAMP; s++) {
        // Output writes on warp1 (state from previous consumer phase).
        if (rank == 0 && warp == 1 && lane == 0) {
            g_idx[b * NSAMP + s]    = cur;
            out_idxf[b * NSAMP + s] = (float)cur;
            float* o = out_xyz + ((size_t)b * NSAMP + s) * 3;
            o[0] = cx; o[1] = cy; o[2] = cz;
        }

        // ---- scan: packed (dx*dx+dy*dy)+dz*dz, rn ordering (bit-match XLA)
        const ull ncx2 = pk(-cx, -cx), ncy2 = pk(-cy, -cy), ncz2 = pk(-cz, -cz);
#pragma unroll
        for (int q = 0; q < NPAIR; q++) {
            const ull dx2 = addx2(x2[q], ncx2);
            const ull dy2 = addx2(y2[q], ncy2);
            const ull dz2 = addx2(z2[q], ncz2);
            const ull d2  = addx2(addx2(mulx2(dx2, dx2), mulx2(dy2, dy2)),
                                  mulx2(dz2, dz2));
            float d0, d1; upk(d2, d0, d1);
            dist[2 * q]     = fminf(dist[2 * q],     d0);
            dist[2 * q + 1] = fminf(dist[2 * q + 1], d1);
        }
        float m = dist[0];
#pragma unroll
        for (int i = 1; i < PPT; i++) m = fmaxf(m, dist[i]);
        const float bd = m;
        int li = 0;
#pragma unroll
        for (int i = PPT - 1; i >= 0; i--) if (dist[i] == bd) li = i;  // first match
        const unsigned bi = (unsigned)(base + tid * PPT + li);

        // ---- warp reduce via redux (dist>=0 => bits monotone; tie -> min idx)
        const unsigned bdb  = __float_as_uint(bd);
        const unsigned wmax = __reduce_max_sync(0xffffffffu, bdb);
        const unsigned wcnd = (bdb == wmax) ? bi : 0x7fffffffu;
        const unsigned wbi  = __reduce_min_sync(0xffffffffu, wcnd);

        // ---- this warp pushes its own slot to all 8 peers (lanes 0..7) ----
        {
            const int lj = (int)wbi - base;                // uniform -> LDS broadcast
            const unsigned wx = __float_as_uint(sx[lj]);
            const unsigned wy = __float_as_uint(sy[lj]);
            const unsigned wz = __float_as_uint(sz[lj]);
            if (lane < CSZ) {
                const unsigned rem = (s & 1) ? rem1 : rem0;
                asm volatile("st.shared::cluster.v2.b32 [%0], {%1,%2};"
                             :: "r"(rem), "r"(wmax), "r"(wx) : "memory");
                asm volatile("st.shared::cluster.v2.b32 [%0], {%1,%2};"
                             :: "r"(rem + 8u), "r"(wy), "r"(wz) : "memory");
                asm volatile("st.release.cluster.shared::cluster.v2.b32 [%0], {%1,%2};"
                             :: "r"(rem + 16u), "r"(wbi), "r"((unsigned)s) : "memory");
            }
        }

        // ---- spin on all 64 tags (2 per lane), then redux over 64 entries
        const unsigned pbase = mb_u + (unsigned)((s & 1) * NSLOT * SLOTB);
        const unsigned a0 = pbase + (unsigned)(lane * SLOTB);
        const unsigned a1 = pbase + (unsigned)((lane + 32) * SLOTB);
        unsigned i0, i1;
        int ok;
        do {
            unsigned t0, t1;
            asm volatile("ld.acquire.cluster.shared::cta.v2.b32 {%0,%1}, [%2];"
                         : "=r"(i0), "=r"(t0) : "r"(a0 + 16u) : "memory");
            asm volatile("ld.acquire.cluster.shared::cta.v2.b32 {%0,%1}, [%2];"
                         : "=r"(i1), "=r"(t1) : "r"(a1 + 16u) : "memory");
            ok = __all_sync(0xffffffffu, (t0 == (unsigned)s) & (t1 == (unsigned)s));
        } while (!ok);

        unsigned d0, d1;
        asm volatile("ld.shared.b32 %0, [%1];" : "=r"(d0) : "r"(a0) : "memory");
        asm volatile("ld.shared.b32 %0, [%1];" : "=r"(d1) : "r"(a1) : "memory");
        // pairwise: max dist, tie -> min idx
        if (d1 > d0 || (d1 == d0 && i1 < i0)) { d0 = d1; i0 = i1; }
        const unsigned gmax = __reduce_max_sync(0xffffffffu, d0);
        const unsigned gcnd = (d0 == gmax) ? i0 : 0x7fffffffu;
        const unsigned wi   = __reduce_min_sync(0xffffffffu, gcnd);
        // winner slot: rank = wi>>12, warp-in-rank = (wi>>9)&7  (512 pts/warp)
        const unsigned wslot = pbase
            + (unsigned)((((wi >> 12) * NWARP) + ((wi >> 9) & 7)) * SLOTB);
        unsigned bx, by, bz;                                // uniform -> broadcast LDS
        asm volatile("ld.shared.b32 %0, [%1];" : "=r"(bx) : "r"(wslot + 4u) : "memory");
        asm volatile("ld.shared.v2.b32 {%0,%1}, [%2];"
                     : "=r"(by), "=r"(bz) : "r"(wslot + 8u) : "memory");
        cur = (int)wi;
        cx = __uint_as_float(bx); cy = __uint_as_float(by); cz = __uint_as_float(bz);
    }
}

// ---------------------------------------------------------------------------
// Feature gather: out_fea[b][c][s] = fea[b][c][g_idx[b][s]]
// ---------------------------------------------------------------------------
__global__ void gather_kernel(const float* __restrict__ fea,
                              float* __restrict__ out_fea)
{
    const int t = blockIdx.x * blockDim.x + threadIdx.x;
    if (t >= BATCH * NCH * NSAMP) return;
    const int s = t % NSAMP;
    const int c = (t / NSAMP) % NCH;
    const int b = t / (NCH * NSAMP);
    const int id = g_idx[b * NSAMP + s];
    out_fea[t] = __ldg(fea + ((size_t)b * NCH + c) * NPTS + id);
}

extern "C" void kernel_launch(void* const* d_in, const int* in_sizes, int n_in,
                              void* d_out, int out_size)
{
    const float* xyz = (const float*)d_in[0];   // (B, N, 3)
    const float* fea = (const float*)d_in[1];   // (B, C, N)

    float* out = (float*)d_out;
    // Output layout: new_xyz (B,S,3) | new_fea (B,C,S) | indices-as-float (B,S)
    float* out_xyz  = out;
    float* out_fea  = out + (size_t)BATCH * NSAMP * 3;
    float* out_idxf = out + (size_t)BATCH * NSAMP * 3 + (size_t)BATCH * NCH * NSAMP;

    const int smem_bytes = 3 * NL * 4            // coord lookup copies
                         + 2 * NSLOT * SLOTB;    // mailbox slots
    cudaFuncSetAttribute(fps_kernel, cudaFuncAttributeMaxDynamicSharedMemorySize, smem_bytes);

    fps_kernel<<<dim3(CSZ, BATCH), T, smem_bytes>>>(xyz, out_xyz, out_idxf);

    const int total = BATCH * NCH * NSAMP;
    gather_kernel<<<(total + 255) / 256, 256>>>(fea, out_fea);
}

// round 13
// speedup vs baseline: 1.1474x; 1.1474x over previous
#include <cuda_runtime.h>
#include <cuda_bf16.h>

#define BATCH 8
#define NPTS  32768
#define NCH   96
#define NSAMP 1024
#define CSZ   8                 // CTAs per batch (cluster)
#define NL    (NPTS / CSZ)      // 4096 points per CTA  (idx>>12 == rank)
#define T     256
#define PPT   (NL / T)          // 16 points per thread
#define NPAIR (PPT / 2)         // 8 packed pairs
#define NWARP (T / 32)          // 8 warps
#define SLOTB 32                // slot: [0]=d [1]=idx [2]=x [3]=y [4]=z [5]=tag

// Scratch (no device allocation allowed).
__device__ int g_idx[BATCH * NSAMP];

// ---------------- packed f32x2 helpers (per-lane IEEE rn => bit-exact) -----
typedef unsigned long long ull;
__device__ __forceinline__ ull pk(float a, float b) {
    ull r; asm("mov.b64 %0, {%1,%2};" : "=l"(r) : "f"(a), "f"(b)); return r;
}
__device__ __forceinline__ void upk(ull v, float& a, float& b) {
    asm("mov.b64 {%0,%1}, %2;" : "=f"(a), "=f"(b) : "l"(v));
}
__device__ __forceinline__ ull addx2(ull a, ull b) {
    ull r; asm("add.rn.f32x2 %0, %1, %2;" : "=l"(r) : "l"(a), "l"(b)); return r;
}
__device__ __forceinline__ ull mulx2(ull a, ull b) {
    ull r; asm("mul.rn.f32x2 %0, %1, %2;" : "=l"(r) : "l"(a), "l"(b)); return r;
}
__device__ __forceinline__ unsigned su32(const void* p) {
    unsigned r;
    asm("{.reg .u64 t; cvta.to.shared.u64 t, %1; cvt.u32.u64 %0, t;}" : "=r"(r) : "l"(p));
    return r;
}

// ---------------------------------------------------------------------------
// FPS: 8-CTA cluster per batch, 256 threads (R10 topology). Packed f32x2
// scan; argmax via redux.max + ballot/ffs (index increases with lane at every
// reduction level, so min-idx tiebreak == lowest tied lane); DSMEM push
// mailbox with {d,idx,x,y | z,tag} slots: consumer gets all winner fields
// from registers via shfl — no post-reduce LDS chain.
// ---------------------------------------------------------------------------
__global__ void __cluster_dims__(CSZ, 1, 1) __launch_bounds__(T, 1)
fps_kernel(const float* __restrict__ xyz,
           float* __restrict__ out_xyz,
           float* __restrict__ out_idxf)
{
    extern __shared__ float smem[];
    float*    sx   = smem;                        // winner-coord lookup copies
    float*    sy   = smem + NL;
    float*    sz   = smem + 2 * NL;
    unsigned* mb   = (unsigned*)(smem + 3 * NL);  // [2][CSZ] slots of 8 u32
    unsigned* swdi = mb + 2 * CSZ * 8;            // per-warp {distbits, idx} v2

    const int rank = blockIdx.x;
    const int b    = blockIdx.y;
    const int tid  = threadIdx.x;
    const int lane = tid & 31;
    const int warp = tid >> 5;
    const int base = rank * NL;
    const float* __restrict__ p = xyz + (size_t)b * NPTS * 3;

    // ---- one-time: load my 16 points -> packed registers + smem lookup copy
    ull x2[NPAIR], y2[NPAIR], z2[NPAIR];
    {
        float buf[48];
        const float4* p4 = (const float4*)(p + (size_t)(base + tid * PPT) * 3);
#pragma unroll
        for (int k = 0; k < 12; k++) ((float4*)buf)[k] = p4[k];
#pragma unroll
        for (int i = 0; i < PPT; i++) {
            sx[tid * PPT + i] = buf[3 * i];
            sy[tid * PPT + i] = buf[3 * i + 1];
            sz[tid * PPT + i] = buf[3 * i + 2];
        }
#pragma unroll
        for (int q = 0; q < NPAIR; q++) {
            x2[q] = pk(buf[6 * q + 0], buf[6 * q + 3]);
            y2[q] = pk(buf[6 * q + 1], buf[6 * q + 4]);
            z2[q] = pk(buf[6 * q + 2], buf[6 * q + 5]);
        }
    }

    // ---- init mailbox tags (word 5 of each slot), then one cluster barrier
    if (tid < 2 * CSZ) mb[tid * 8 + 5] = 0xFFFFFFFFu;
    __syncthreads();
    asm volatile("barrier.cluster.arrive.aligned;\n" ::: "memory");
    asm volatile("barrier.cluster.wait.aligned;\n"   ::: "memory");

    const unsigned mb_u   = su32(mb);
    const unsigned swdi_u = su32(swdi);

    // Remote slot addresses: warp0 lane r pushes into peer r's slot[parity][rank].
    unsigned rem0 = 0, rem1 = 0;
    if (warp == 0 && lane < CSZ) {
        const unsigned l0 = mb_u + (unsigned)((0 * CSZ + rank) * SLOTB);
        const unsigned l1 = mb_u + (unsigned)((1 * CSZ + rank) * SLOTB);
        asm("mapa.shared::cluster.u32 %0, %1, %2;" : "=r"(rem0) : "r"(l0), "r"(lane));
        asm("mapa.shared::cluster.u32 %0, %1, %2;" : "=r"(rem1) : "r"(l1), "r"(lane));
    }

    float dist[PPT];
#pragma unroll
    for (int i = 0; i < PPT; i++) dist[i] = 1e10f;

    int   cur = 0;
    float cx = __ldg(p + 0), cy = __ldg(p + 1), cz = __ldg(p + 2);

    for (int s = 0; s < NSAMP; s++) {
        // Output writes on a non-critical warp (warp1), state from prev iter.
        if (rank == 0 && warp == 1 && lane == 0) {
            g_idx[b * NSAMP + s]    = cur;
            out_idxf[b * NSAMP + s] = (float)cur;
            float* o = out_xyz + ((size_t)b * NSAMP + s) * 3;
            o[0] = cx; o[1] = cy; o[2] = cz;
        }

        // ---- scan: packed (dx*dx+dy*dy)+dz*dz, rn ordering (bit-match XLA)
        const ull ncx2 = pk(-cx, -cx), ncy2 = pk(-cy, -cy), ncz2 = pk(-cz, -cz);
#pragma unroll
        for (int q = 0; q < NPAIR; q++) {
            const ull dx2 = addx2(x2[q], ncx2);
            const ull dy2 = addx2(y2[q], ncy2);
            const ull dz2 = addx2(z2[q], ncz2);
            const ull d2  = addx2(addx2(mulx2(dx2, dx2), mulx2(dy2, dy2)),
                                  mulx2(dz2, dz2));
            float d0, d1; upk(d2, d0, d1);
            dist[2 * q]     = fminf(dist[2 * q],     d0);
            dist[2 * q + 1] = fminf(dist[2 * q + 1], d1);
        }
        float m = dist[0];
#pragma unroll
        for (int i = 1; i < PPT; i++) m = fmaxf(m, dist[i]);
        const float bd = m;
        int li = 0;
#pragma unroll
        for (int i = PPT - 1; i >= 0; i--) if (dist[i] == bd) li = i;  // first match
        const unsigned bi = (unsigned)(base + tid * PPT + li);

        // ---- warp reduce: redux.max + ballot (idx increases with lane =>
        //      min-idx tie-break == lowest tied lane)
        const unsigned bdb  = __float_as_uint(bd);
        const unsigned wmax = __reduce_max_sync(0xffffffffu, bdb);
        const unsigned wbal = __ballot_sync(0xffffffffu, bdb == wmax);
        const unsigned wbi  = __shfl_sync(0xffffffffu, bi, __ffs(wbal) - 1);
        if (lane == 0)
            asm volatile("st.shared.v2.b32 [%0], {%1,%2};"
                         :: "r"(swdi_u + (unsigned)(warp * 8)), "r"(wmax), "r"(wbi)
                         : "memory");
        __syncthreads();

        // ---- warp0: CTA reduce (8 warp results; idx increases with lane) +
        //      DSMEM push: v4 {d,idx,x,y} then release v2 {z,tag}
        if (warp == 0) {
            unsigned v = 0, i = 0x7fffffffu;
            if (lane < NWARP)
                asm volatile("ld.shared.v2.b32 {%0,%1}, [%2];"
                             : "=r"(v), "=r"(i)
                             : "r"(swdi_u + (unsigned)(lane * 8)) : "memory");
            const unsigned cmax = __reduce_max_sync(0xffffffffu, v);
            const unsigned cbal = __ballot_sync(0xffffffffu, (v == cmax) && (lane < NWARP));
            const unsigned ri   = __shfl_sync(0xffffffffu, i, __ffs(cbal) - 1);
            const int lj = (int)ri - base;                 // uniform -> LDS broadcast
            const unsigned wx = __float_as_uint(sx[lj]);
            const unsigned wy = __float_as_uint(sy[lj]);
            const unsigned wz = __float_as_uint(sz[lj]);
            if (lane < CSZ) {
                const unsigned rem = (s & 1) ? rem1 : rem0;
                asm volatile("st.shared::cluster.v4.b32 [%0], {%1,%2,%3,%4};"
                             :: "r"(rem), "r"(cmax), "r"(ri), "r"(wx), "r"(wy)
                             : "memory");
                asm volatile("st.release.cluster.shared::cluster.v2.b32 [%0], {%1,%2};"
                             :: "r"(rem + 16u), "r"(wz), "r"((unsigned)s) : "memory");
            }
        }

        // ---- every warp: spin on {z,tag} acquire v2, then weak v4 data load;
        //      winner fields broadcast via shfl (no post-reduce LDS chain)
        const unsigned slot_a = mb_u + (unsigned)(((s & 1) * CSZ + lane) * SLOTB);
        unsigned rz = 0;
        int ok;
        do {
            unsigned tg = (unsigned)s, z_ = 0;
            if (lane < CSZ)
                asm volatile("ld.acquire.cluster.shared::cta.v2.b32 {%0,%1}, [%2];"
                             : "=r"(z_), "=r"(tg) : "r"(slot_a + 16u) : "memory");
            ok = __all_sync(0xffffffffu, tg == (unsigned)s);
            rz = z_;
        } while (!ok);

        unsigned rd = 0, ridx = 0x7fffffffu, rx = 0, ry = 0;
        if (lane < CSZ)
            asm volatile("ld.shared.v4.b32 {%0,%1,%2,%3}, [%4];"
                         : "=r"(rd), "=r"(ridx), "=r"(rx), "=r"(ry)
                         : "r"(slot_a) : "memory");
        // lane == rank, idx in [lane*NL,(lane+1)*NL) => increasing with lane
        const unsigned gmax = __reduce_max_sync(0xffffffffu, rd);
        const unsigned gbal = __ballot_sync(0xffffffffu, (rd == gmax) && (lane < CSZ));
        const int      src  = __ffs(gbal) - 1;
        cur = (int)__shfl_sync(0xffffffffu, ridx, src);
        cx  = __uint_as_float(__shfl_sync(0xffffffffu, rx, src));
        cy  = __uint_as_float(__shfl_sync(0xffffffffu, ry, src));
        cz  = __uint_as_float(__shfl_sync(0xffffffffu, rz, src));
    }
}

// ---------------------------------------------------------------------------
// Feature gather: out_fea[b][c][s] = fea[b][c][g_idx[b][s]]
// ---------------------------------------------------------------------------
__global__ void gather_kernel(const float* __restrict__ fea,
                              float* __restrict__ out_fea)
{
    const int t = blockIdx.x * blockDim.x + threadIdx.x;
    if (t >= BATCH * NCH * NSAMP) return;
    const int s = t % NSAMP;
    const int c = (t / NSAMP) % NCH;
    const int b = t / (NCH * NSAMP);
    const int id = g_idx[b * NSAMP + s];
    out_fea[t] = __ldg(fea + ((size_t)b * NCH + c) * NPTS + id);
}

extern "C" void kernel_launch(void* const* d_in, const int* in_sizes, int n_in,
                              void* d_out, int out_size)
{
    const float* xyz = (const float*)d_in[0];   // (B, N, 3)
    const float* fea = (const float*)d_in[1];   // (B, C, N)

    float* out = (float*)d_out;
    // Output layout: new_xyz (B,S,3) | new_fea (B,C,S) | indices-as-float (B,S)
    float* out_xyz  = out;
    float* out_fea  = out + (size_t)BATCH * NSAMP * 3;
    float* out_idxf = out + (size_t)BATCH * NSAMP * 3 + (size_t)BATCH * NCH * NSAMP;

    const int smem_bytes = 3 * NL * 4            // coord lookup copies
                         + 2 * CSZ * SLOTB      // mailbox slots
                         + NWARP * 8;            // per-warp {d,idx} v2 scratch
    cudaFuncSetAttribute(fps_kernel, cudaFuncAttributeMaxDynamicSharedMemorySize, smem_bytes);

    fps_kernel<<<dim3(CSZ, BATCH), T, smem_bytes>>>(xyz, out_xyz, out_idxf);

    const int total = BATCH * NCH * NSAMP;
    gather_kernel<<<(total + 255) / 256, 256>>>(fea, out_fea);
}

// round 14
// speedup vs baseline: 1.1597x; 1.0107x over previous
#include <cuda_runtime.h>
#include <cuda_bf16.h>

#define BATCH 8
#define NPTS  32768
#define NCH   96
#define NSAMP 1024
#define CSZ   8                 // CTAs per batch (cluster)
#define NL    (NPTS / CSZ)      // 4096 points per CTA  (idx>>12 == rank)
#define T     256
#define PPT   (NL / T)          // 16 points per thread
#define NPAIR (PPT / 2)         // 8 packed pairs
#define NWARP (T / 32)          // 8 warps
#define SLOTB 24                // mailbox slot bytes: {d,x | y,z | idx,pad}

// Scratch (no device allocation allowed).
__device__ int g_idx[BATCH * NSAMP];

// ---------------- packed f32x2 helpers (per-lane IEEE rn => bit-exact) -----
typedef unsigned long long ull;
__device__ __forceinline__ ull pk(float a, float b) {
    ull r; asm("mov.b64 %0, {%1,%2};" : "=l"(r) : "f"(a), "f"(b)); return r;
}
__device__ __forceinline__ void upk(ull v, float& a, float& b) {
    asm("mov.b64 {%0,%1}, %2;" : "=f"(a), "=f"(b) : "l"(v));
}
__device__ __forceinline__ ull addx2(ull a, ull b) {
    ull r; asm("add.rn.f32x2 %0, %1, %2;" : "=l"(r) : "l"(a), "l"(b)); return r;
}
__device__ __forceinline__ ull mulx2(ull a, ull b) {
    ull r; asm("mul.rn.f32x2 %0, %1, %2;" : "=l"(r) : "l"(a), "l"(b)); return r;
}
__device__ __forceinline__ unsigned su32(const void* p) {
    unsigned r;
    asm("{.reg .u64 t; cvta.to.shared.u64 t, %1; cvt.u32.u64 %0, t;}" : "=r"(r) : "l"(p));
    return r;
}

// ---------------------------------------------------------------------------
// FPS: 8-CTA cluster per batch, 256 threads/CTA (R10 topology). Coords in
// registers (packed f32x2 scan); argmax at all levels via redux.sync
// (dist>=0 => u32-monotonic bits; tie -> min index); DSMEM push mailbox.
// SINGLE CHANGE vs R10: notification via per-parity mbarriers (producers
// arrive.release on each peer's mbar; consumers try_wait.parity HW-sleep)
// instead of the tag spin loop.
// ---------------------------------------------------------------------------
__global__ void __cluster_dims__(CSZ, 1, 1) __launch_bounds__(T, 1)
fps_kernel(const float* __restrict__ xyz,
           float* __restrict__ out_xyz,
           float* __restrict__ out_idxf)
{
    extern __shared__ float smem[];
    float*    sx   = smem;                        // winner-coord lookup copies
    float*    sy   = smem + NL;
    float*    sz   = smem + 2 * NL;
    unsigned* mbar = (unsigned*)(smem + 3 * NL);  // 2 mbarriers (u64 each)
    unsigned* mb   = mbar + 4;                    // [2][CSZ] slots of 6 u32
    unsigned* swdi = mb + 2 * CSZ * 6;            // per-warp {distbits, idx} v2

    const int rank = blockIdx.x;
    const int b    = blockIdx.y;
    const int tid  = threadIdx.x;
    const int lane = tid & 31;
    const int warp = tid >> 5;
    const int base = rank * NL;
    const float* __restrict__ p = xyz + (size_t)b * NPTS * 3;

    // ---- one-time: load my 16 points -> packed registers + smem lookup copy
    ull x2[NPAIR], y2[NPAIR], z2[NPAIR];
    {
        float buf[48];
        const float4* p4 = (const float4*)(p + (size_t)(base + tid * PPT) * 3);
#pragma unroll
        for (int k = 0; k < 12; k++) ((float4*)buf)[k] = p4[k];
#pragma unroll
        for (int i = 0; i < PPT; i++) {
            sx[tid * PPT + i] = buf[3 * i];
            sy[tid * PPT + i] = buf[3 * i + 1];
            sz[tid * PPT + i] = buf[3 * i + 2];
        }
#pragma unroll
        for (int q = 0; q < NPAIR; q++) {
            x2[q] = pk(buf[6 * q + 0], buf[6 * q + 3]);
            y2[q] = pk(buf[6 * q + 1], buf[6 * q + 4]);
            z2[q] = pk(buf[6 * q + 2], buf[6 * q + 5]);
        }
    }

    const unsigned mbar_u = su32(mbar);
    const unsigned mb_u   = su32(mb);
    const unsigned swdi_u = su32(swdi);

    // ---- init mbarriers (count = CSZ producers each), then cluster barrier
    if (tid == 0) {
        asm volatile("mbarrier.init.shared.b64 [%0], %1;"
                     :: "r"(mbar_u),      "r"((unsigned)CSZ) : "memory");
        asm volatile("mbarrier.init.shared.b64 [%0], %1;"
                     :: "r"(mbar_u + 8u), "r"((unsigned)CSZ) : "memory");
    }
    __syncthreads();
    asm volatile("barrier.cluster.arrive.aligned;\n" ::: "memory");
    asm volatile("barrier.cluster.wait.aligned;\n"   ::: "memory");

    // Remote addresses: warp0 lane r pushes into peer r's slot[parity][rank]
    // and arrives on peer r's mbar[parity].
    unsigned rem0 = 0, rem1 = 0, remb0 = 0, remb1 = 0;
    if (warp == 0 && lane < CSZ) {
        const unsigned l0 = mb_u + (unsigned)((0 * CSZ + rank) * SLOTB);
        const unsigned l1 = mb_u + (unsigned)((1 * CSZ + rank) * SLOTB);
        asm("mapa.shared::cluster.u32 %0, %1, %2;" : "=r"(rem0)  : "r"(l0), "r"(lane));
        asm("mapa.shared::cluster.u32 %0, %1, %2;" : "=r"(rem1)  : "r"(l1), "r"(lane));
        asm("mapa.shared::cluster.u32 %0, %1, %2;" : "=r"(remb0) : "r"(mbar_u),      "r"(lane));
        asm("mapa.shared::cluster.u32 %0, %1, %2;" : "=r"(remb1) : "r"(mbar_u + 8u), "r"(lane));
    }

    float dist[PPT];
#pragma unroll
    for (int i = 0; i < PPT; i++) dist[i] = 1e10f;

    int   cur = 0;
    float cx = __ldg(p + 0), cy = __ldg(p + 1), cz = __ldg(p + 2);

    for (int s = 0; s < NSAMP; s++) {
        // Output writes on a non-critical warp (warp1), state from prev iter.
        if (rank == 0 && warp == 1 && lane == 0) {
            g_idx[b * NSAMP + s]    = cur;
            out_idxf[b * NSAMP + s] = (float)cur;
            float* o = out_xyz + ((size_t)b * NSAMP + s) * 3;
            o[0] = cx; o[1] = cy; o[2] = cz;
        }

        // ---- scan: packed (dx*dx+dy*dy)+dz*dz, rn ordering (bit-match XLA)
        const ull ncx2 = pk(-cx, -cx), ncy2 = pk(-cy, -cy), ncz2 = pk(-cz, -cz);
#pragma unroll
        for (int q = 0; q < NPAIR; q++) {
            const ull dx2 = addx2(x2[q], ncx2);
            const ull dy2 = addx2(y2[q], ncy2);
            const ull dz2 = addx2(z2[q], ncz2);
            const ull d2  = addx2(addx2(mulx2(dx2, dx2), mulx2(dy2, dy2)),
                                  mulx2(dz2, dz2));
            float d0, d1; upk(d2, d0, d1);
            dist[2 * q]     = fminf(dist[2 * q],     d0);
            dist[2 * q + 1] = fminf(dist[2 * q + 1], d1);
        }
        float m = dist[0];
#pragma unroll
        for (int i = 1; i < PPT; i++) m = fmaxf(m, dist[i]);
        const float bd = m;
        int li = 0;
#pragma unroll
        for (int i = PPT - 1; i >= 0; i--) if (dist[i] == bd) li = i;  // first match
        const unsigned bi = (unsigned)(base + tid * PPT + li);

        // ---- warp reduce via redux (dist>=0 => bits monotone; tie -> min idx)
        const unsigned bdb  = __float_as_uint(bd);
        const unsigned wmax = __reduce_max_sync(0xffffffffu, bdb);
        const unsigned wcnd = (bdb == wmax) ? bi : 0x7fffffffu;
        const unsigned wbi  = __reduce_min_sync(0xffffffffu, wcnd);
        if (lane == 0)
            asm volatile("st.shared.v2.b32 [%0], {%1,%2};"
                         :: "r"(swdi_u + (unsigned)(warp * 8)), "r"(wmax), "r"(wbi)
                         : "memory");
        __syncthreads();

        // ---- warp0: CTA reduce (8 warp results) + DSMEM push + remote arrive
        if (warp == 0) {
            unsigned v = 0, i = 0x7fffffffu;
            if (lane < NWARP)
                asm volatile("ld.shared.v2.b32 {%0,%1}, [%2];"
                             : "=r"(v), "=r"(i)
                             : "r"(swdi_u + (unsigned)(lane * 8)) : "memory");
            const unsigned cmax = __reduce_max_sync(0xffffffffu, v);
            const unsigned ccnd = (v == cmax) ? i : 0x7fffffffu;
            const unsigned ri   = __reduce_min_sync(0xffffffffu, ccnd);
            const int lj = (int)ri - base;                 // uniform -> LDS broadcast
            const unsigned wx = __float_as_uint(sx[lj]);
            const unsigned wy = __float_as_uint(sy[lj]);
            const unsigned wz = __float_as_uint(sz[lj]);
            if (lane < CSZ) {
                const unsigned rem  = (s & 1) ? rem1  : rem0;
                const unsigned remb = (s & 1) ? remb1 : remb0;
                asm volatile("st.shared::cluster.v2.b32 [%0], {%1,%2};"
                             :: "r"(rem), "r"(cmax), "r"(wx) : "memory");
                asm volatile("st.shared::cluster.v2.b32 [%0], {%1,%2};"
                             :: "r"(rem + 8u), "r"(wy), "r"(wz) : "memory");
                asm volatile("st.shared::cluster.u32 [%0], %1;"
                             :: "r"(rem + 16u), "r"(ri) : "memory");
                asm volatile("mbarrier.arrive.release.cluster.shared::cluster.b64 _, [%0];"
                             :: "r"(remb) : "memory");
            }
        }

        // ---- every warp: mbarrier try_wait (HW sleep), then redux over 8 CTAs
        {
            const unsigned ba  = mbar_u + (unsigned)((s & 1) * 8);
            const unsigned par = (unsigned)((s >> 1) & 1);
            unsigned done;
            asm volatile("{\n\t.reg .pred p;\n\t"
                         "mbarrier.try_wait.parity.acquire.cluster.shared::cta.b64 p, [%1], %2;\n\t"
                         "selp.b32 %0, 1, 0, p;\n\t}"
                         : "=r"(done) : "r"(ba), "r"(par) : "memory");
            while (!done) {
                asm volatile("{\n\t.reg .pred p;\n\t"
                             "mbarrier.try_wait.parity.acquire.cluster.shared::cta.b64 p, [%1], %2, 0x989680;\n\t"
                             "selp.b32 %0, 1, 0, p;\n\t}"
                             : "=r"(done) : "r"(ba), "r"(par) : "memory");
            }
        }

        const unsigned slot_a = mb_u + (unsigned)(((s & 1) * CSZ + lane) * SLOTB);
        unsigned db = 0, ridx = 0x7fffffffu;
        if (lane < CSZ) {
            asm volatile("ld.shared.b32 %0, [%1];" : "=r"(db)   : "r"(slot_a)       : "memory");
            asm volatile("ld.shared.b32 %0, [%1];" : "=r"(ridx) : "r"(slot_a + 16u) : "memory");
        }
        const unsigned gmax = __reduce_max_sync(0xffffffffu, db);
        const unsigned gcnd = (lane < CSZ && db == gmax) ? ridx : 0x7fffffffu;
        const unsigned wi   = __reduce_min_sync(0xffffffffu, gcnd);
        const unsigned wslot = mb_u + (unsigned)(((s & 1) * CSZ + (wi >> 12)) * SLOTB);
        unsigned bx, by, bz;                                // uniform -> broadcast LDS
        asm volatile("ld.shared.b32 %0, [%1];" : "=r"(bx) : "r"(wslot + 4u) : "memory");
        asm volatile("ld.shared.v2.b32 {%0,%1}, [%2];"
                     : "=r"(by), "=r"(bz) : "r"(wslot + 8u) : "memory");
        cur = (int)wi;
        cx = __uint_as_float(bx); cy = __uint_as_float(by); cz = __uint_as_float(bz);
    }
}

// ---------------------------------------------------------------------------
// Feature gather: out_fea[b][c][s] = fea[b][c][g_idx[b][s]]
// ---------------------------------------------------------------------------
__global__ void gather_kernel(const float* __restrict__ fea,
                              float* __restrict__ out_fea)
{
    const int t = blockIdx.x * blockDim.x + threadIdx.x;
    if (t >= BATCH * NCH * NSAMP) return;
    const int s = t % NSAMP;
    const int c = (t / NSAMP) % NCH;
    const int b = t / (NCH * NSAMP);
    const int id = g_idx[b * NSAMP + s];
    out_fea[t] = __ldg(fea + ((size_t)b * NCH + c) * NPTS + id);
}

extern "C" void kernel_launch(void* const* d_in, const int* in_sizes, int n_in,
                              void* d_out, int out_size)
{
    const float* xyz = (const float*)d_in[0];   // (B, N, 3)
    const float* fea = (const float*)d_in[1];   // (B, C, N)

    float* out = (float*)d_out;
    // Output layout: new_xyz (B,S,3) | new_fea (B,C,S) | indices-as-float (B,S)
    float* out_xyz  = out;
    float* out_fea  = out + (size_t)BATCH * NSAMP * 3;
    float* out_idxf = out + (size_t)BATCH * NSAMP * 3 + (size_t)BATCH * NCH * NSAMP;

    const int smem_bytes = 3 * NL * 4            // coord lookup copies
                         + 16                    // 2 mbarriers
                         + 2 * CSZ * SLOTB       // mailbox slots
                         + NWARP * 8;            // per-warp {d,idx} v2 scratch
    cudaFuncSetAttribute(fps_kernel, cudaFuncAttributeMaxDynamicSharedMemorySize, smem_bytes);

    fps_kernel<<<dim3(CSZ, BATCH), T, smem_bytes>>>(xyz, out_xyz, out_idxf);

    const int total = BATCH * NCH * NSAMP;
    gather_kernel<<<(total + 255) / 256, 256>>>(fea, out_fea);
}

// round 15
// speedup vs baseline: 1.2018x; 1.0363x over previous
#include <cuda_runtime.h>
#include <cuda_bf16.h>

#define BATCH 8
#define NPTS  32768
#define NCH   96
#define NSAMP 1024
#define CSZ   8                 // CTAs per batch (cluster)
#define NL    (NPTS / CSZ)      // 4096 points per CTA  (idx>>12 == rank)
#define T     256
#define PPT   (NL / T)          // 16 points per thread
#define NPAIR (PPT / 2)         // 8 packed pairs
#define NWARP (T / 32)          // 8 warps
#define SLOTB 24                // slot: [0]=d [1]=idx [2]=x [3]=y [4]=z [5]=tag

// Scratch (no device allocation allowed).
__device__ int g_idx[BATCH * NSAMP];

// ---------------- packed f32x2 helpers (per-lane IEEE rn => bit-exact) -----
typedef unsigned long long ull;
__device__ __forceinline__ ull pk(float a, float b) {
    ull r; asm("mov.b64 %0, {%1,%2};" : "=l"(r) : "f"(a), "f"(b)); return r;
}
__device__ __forceinline__ void upk(ull v, float& a, float& b) {
    asm("mov.b64 {%0,%1}, %2;" : "=f"(a), "=f"(b) : "l"(v));
}
__device__ __forceinline__ ull addx2(ull a, ull b) {
    ull r; asm("add.rn.f32x2 %0, %1, %2;" : "=l"(r) : "l"(a), "l"(b)); return r;
}
__device__ __forceinline__ ull mulx2(ull a, ull b) {
    ull r; asm("mul.rn.f32x2 %0, %1, %2;" : "=l"(r) : "l"(a), "l"(b)); return r;
}
__device__ __forceinline__ unsigned su32(const void* p) {
    unsigned r;
    asm("{.reg .u64 t; cvta.to.shared.u64 t, %1; cvt.u32.u64 %0, t;}" : "=r"(r) : "l"(p));
    return r;
}

// ---------------------------------------------------------------------------
// FPS: 8-CTA cluster per batch, 256 threads/CTA (R10 topology, tag-spin).
// SINGLE CHANGE vs R10 (862us): slot layout {d,idx | x,y | z,tag} so the
// consumer's spin read yields z, {d,idx} is one v2 LDS, winner z comes via
// shfl from the winner rank's lane, and winner {x,y} is one v2 LDS —
// collapsing 4 serialized consumer loads to 2. Producer unchanged (3x v2).
// ---------------------------------------------------------------------------
__global__ void __cluster_dims__(CSZ, 1, 1) __launch_bounds__(T, 1)
fps_kernel(const float* __restrict__ xyz,
           float* __restrict__ out_xyz,
           float* __restrict__ out_idxf)
{
    extern __shared__ float smem[];
    float*    sx   = smem;                        // winner-coord lookup copies
    float*    sy   = smem + NL;
    float*    sz   = smem + 2 * NL;
    unsigned* mb   = (unsigned*)(smem + 3 * NL);  // [2][CSZ] slots of 6 u32
    unsigned* swdi = mb + 2 * CSZ * 6;            // per-warp {distbits, idx} v2

    const int rank = blockIdx.x;
    const int b    = blockIdx.y;
    const int tid  = threadIdx.x;
    const int lane = tid & 31;
    const int warp = tid >> 5;
    const int base = rank * NL;
    const float* __restrict__ p = xyz + (size_t)b * NPTS * 3;

    // ---- one-time: load my 16 points -> packed registers + smem lookup copy
    ull x2[NPAIR], y2[NPAIR], z2[NPAIR];
    {
        float buf[48];
        const float4* p4 = (const float4*)(p + (size_t)(base + tid * PPT) * 3);
#pragma unroll
        for (int k = 0; k < 12; k++) ((float4*)buf)[k] = p4[k];
#pragma unroll
        for (int i = 0; i < PPT; i++) {
            sx[tid * PPT + i] = buf[3 * i];
            sy[tid * PPT + i] = buf[3 * i + 1];
            sz[tid * PPT + i] = buf[3 * i + 2];
        }
#pragma unroll
        for (int q = 0; q < NPAIR; q++) {
            x2[q] = pk(buf[6 * q + 0], buf[6 * q + 3]);
            y2[q] = pk(buf[6 * q + 1], buf[6 * q + 4]);
            z2[q] = pk(buf[6 * q + 2], buf[6 * q + 5]);
        }
    }

    // ---- init mailbox tags (word 5 of each slot), then one cluster barrier
    if (tid < 2 * CSZ) mb[tid * 6 + 5] = 0xFFFFFFFFu;
    __syncthreads();
    asm volatile("barrier.cluster.arrive.aligned;\n" ::: "memory");
    asm volatile("barrier.cluster.wait.aligned;\n"   ::: "memory");

    const unsigned mb_u   = su32(mb);
    const unsigned swdi_u = su32(swdi);

    // Remote slot addresses: warp0 lane r pushes into peer r's slot[parity][rank].
    unsigned rem0 = 0, rem1 = 0;
    if (warp == 0 && lane < CSZ) {
        const unsigned l0 = mb_u + (unsigned)((0 * CSZ + rank) * SLOTB);
        const unsigned l1 = mb_u + (unsigned)((1 * CSZ + rank) * SLOTB);
        asm("mapa.shared::cluster.u32 %0, %1, %2;" : "=r"(rem0) : "r"(l0), "r"(lane));
        asm("mapa.shared::cluster.u32 %0, %1, %2;" : "=r"(rem1) : "r"(l1), "r"(lane));
    }

    float dist[PPT];
#pragma unroll
    for (int i = 0; i < PPT; i++) dist[i] = 1e10f;

    int   cur = 0;
    float cx = __ldg(p + 0), cy = __ldg(p + 1), cz = __ldg(p + 2);

    for (int s = 0; s < NSAMP; s++) {
        // Output writes on a non-critical warp (warp1), state from prev iter.
        if (rank == 0 && warp == 1 && lane == 0) {
            g_idx[b * NSAMP + s]    = cur;
            out_idxf[b * NSAMP + s] = (float)cur;
            float* o = out_xyz + ((size_t)b * NSAMP + s) * 3;
            o[0] = cx; o[1] = cy; o[2] = cz;
        }

        // ---- scan: packed (dx*dx+dy*dy)+dz*dz, rn ordering (bit-match XLA)
        const ull ncx2 = pk(-cx, -cx), ncy2 = pk(-cy, -cy), ncz2 = pk(-cz, -cz);
#pragma unroll
        for (int q = 0; q < NPAIR; q++) {
            const ull dx2 = addx2(x2[q], ncx2);
            const ull dy2 = addx2(y2[q], ncy2);
            const ull dz2 = addx2(z2[q], ncz2);
            const ull d2  = addx2(addx2(mulx2(dx2, dx2), mulx2(dy2, dy2)),
                                  mulx2(dz2, dz2));
            float d0, d1; upk(d2, d0, d1);
            dist[2 * q]     = fminf(dist[2 * q],     d0);
            dist[2 * q + 1] = fminf(dist[2 * q + 1], d1);
        }
        float m = dist[0];
#pragma unroll
        for (int i = 1; i < PPT; i++) m = fmaxf(m, dist[i]);
        const float bd = m;
        int li = 0;
#pragma unroll
        for (int i = PPT - 1; i >= 0; i--) if (dist[i] == bd) li = i;  // first match
        const unsigned bi = (unsigned)(base + tid * PPT + li);

        // ---- warp reduce via redux (dist>=0 => bits monotone; tie -> min idx)
        const unsigned bdb  = __float_as_uint(bd);
        const unsigned wmax = __reduce_max_sync(0xffffffffu, bdb);
        const unsigned wcnd = (bdb == wmax) ? bi : 0x7fffffffu;
        const unsigned wbi  = __reduce_min_sync(0xffffffffu, wcnd);
        if (lane == 0)
            asm volatile("st.shared.v2.b32 [%0], {%1,%2};"
                         :: "r"(swdi_u + (unsigned)(warp * 8)), "r"(wmax), "r"(wbi)
                         : "memory");
        __syncthreads();

        // ---- warp0: CTA reduce (8 warp results) + DSMEM push ----
        if (warp == 0) {
            unsigned v = 0, i = 0x7fffffffu;
            if (lane < NWARP)
                asm volatile("ld.shared.v2.b32 {%0,%1}, [%2];"
                             : "=r"(v), "=r"(i)
                             : "r"(swdi_u + (unsigned)(lane * 8)) : "memory");
            const unsigned cmax = __reduce_max_sync(0xffffffffu, v);
            const unsigned ccnd = (v == cmax) ? i : 0x7fffffffu;
            const unsigned ri   = __reduce_min_sync(0xffffffffu, ccnd);
            const int lj = (int)ri - base;                 // uniform -> LDS broadcast
            const unsigned wx = __float_as_uint(sx[lj]);
            const unsigned wy = __float_as_uint(sy[lj]);
            const unsigned wz = __float_as_uint(sz[lj]);
            if (lane < CSZ) {
                const unsigned rem = (s & 1) ? rem1 : rem0;
                asm volatile("st.shared::cluster.v2.b32 [%0], {%1,%2};"
                             :: "r"(rem), "r"(cmax), "r"(ri) : "memory");
                asm volatile("st.shared::cluster.v2.b32 [%0], {%1,%2};"
                             :: "r"(rem + 8u), "r"(wx), "r"(wy) : "memory");
                asm volatile("st.release.cluster.shared::cluster.v2.b32 [%0], {%1,%2};"
                             :: "r"(rem + 16u), "r"(wz), "r"((unsigned)s) : "memory");
            }
        }

        // ---- every warp: spin on {z,tag}; z rides the spin word ----
        const unsigned slot_a = mb_u + (unsigned)(((s & 1) * CSZ + lane) * SLOTB);
        unsigned rz = 0;
        int ok;
        do {
            unsigned tg = (unsigned)s, z_ = 0;
            if (lane < CSZ)
                asm volatile("ld.acquire.cluster.shared::cta.v2.b32 {%0,%1}, [%2];"
                             : "=r"(z_), "=r"(tg) : "r"(slot_a + 16u) : "memory");
            ok = __all_sync(0xffffffffu, tg == (unsigned)s);
            rz = z_;
        } while (!ok);

        unsigned db = 0, ridx = 0x7fffffffu;
        if (lane < CSZ)
            asm volatile("ld.shared.v2.b32 {%0,%1}, [%2];"
                         : "=r"(db), "=r"(ridx) : "r"(slot_a) : "memory");
        const unsigned gmax = __reduce_max_sync(0xffffffffu, db);
        const unsigned gcnd = (lane < CSZ && db == gmax) ? ridx : 0x7fffffffu;
        const unsigned wi   = __reduce_min_sync(0xffffffffu, gcnd);
        const int      wr   = (int)(wi >> 12);             // winner rank == lane
        // winner z via shfl; winner {x,y} via one broadcast v2 LDS
        cz = __uint_as_float(__shfl_sync(0xffffffffu, rz, wr));
        const unsigned wslot = mb_u + (unsigned)(((s & 1) * CSZ + wr) * SLOTB);
        unsigned bx, by;
        asm volatile("ld.shared.v2.b32 {%0,%1}, [%2];"
                     : "=r"(bx), "=r"(by) : "r"(wslot + 8u) : "memory");
        cur = (int)wi;
        cx = __uint_as_float(bx); cy = __uint_as_float(by);
    }
}

// ---------------------------------------------------------------------------
// Feature gather: out_fea[b][c][s] = fea[b][c][g_idx[b][s]]
// ---------------------------------------------------------------------------
__global__ void gather_kernel(const float* __restrict__ fea,
                              float* __restrict__ out_fea)
{
    const int t = blockIdx.x * blockDim.x + threadIdx.x;
    if (t >= BATCH * NCH * NSAMP) return;
    const int s = t % NSAMP;
    const int c = (t / NSAMP) % NCH;
    const int b = t / (NCH * NSAMP);
    const int id = g_idx[b * NSAMP + s];
    out_fea[t] = __ldg(fea + ((size_t)b * NCH + c) * NPTS + id);
}

extern "C" void kernel_launch(void* const* d_in, const int* in_sizes, int n_in,
                              void* d_out, int out_size)
{
    const float* xyz = (const float*)d_in[0];   // (B, N, 3)
    const float* fea = (const float*)d_in[1];   // (B, C, N)

    float* out = (float*)d_out;
    // Output layout: new_xyz (B,S,3) | new_fea (B,C,S) | indices-as-float (B,S)
    float* out_xyz  = out;
    float* out_fea  = out + (size_t)BATCH * NSAMP * 3;
    float* out_idxf = out + (size_t)BATCH * NSAMP * 3 + (size_t)BATCH * NCH * NSAMP;

    const int smem_bytes = 3 * NL * 4            // coord lookup copies
                         + 2 * CSZ * SLOTB       // mailbox slots
                         + NWARP * 8;            // per-warp {d,idx} v2 scratch
    cudaFuncSetAttribute(fps_kernel, cudaFuncAttributeMaxDynamicSharedMemorySize, smem_bytes);

    fps_kernel<<<dim3(CSZ, BATCH), T, smem_bytes>>>(xyz, out_xyz, out_idxf);

    const int total = BATCH * NCH * NSAMP;
    gather_kernel<<<(total + 255) / 256, 256>>>(fea, out_fea);
}

// round 17
// speedup vs baseline: 1.2052x; 1.0028x over previous
#include <cuda_runtime.h>
#include <cuda_bf16.h>

#define BATCH 8
#define NPTS  32768
#define NCH   96
#define NSAMP 1024
#define CSZ   8                 // CTAs per batch (cluster)
#define NL    (NPTS / CSZ)      // 4096 points per CTA  (idx>>12 == rank)
#define T     256
#define PPT   (NL / T)          // 16 points per thread
#define NPAIR (PPT / 2)         // 8 packed pairs
#define NWARP (T / 32)          // 8 warps
#define SLOTB 24                // slot: [0]=d [1]=idx [2]=x [3]=y [4]=z [5]=tag

// Scratch (no device allocation allowed).
__device__ int g_idx[BATCH * NSAMP];

// ---------------- packed f32x2 helpers (per-lane IEEE rn => bit-exact) -----
typedef unsigned long long ull;
__device__ __forceinline__ ull pk(float a, float b) {
    ull r; asm("mov.b64 %0, {%1,%2};" : "=l"(r) : "f"(a), "f"(b)); return r;
}
__device__ __forceinline__ void upk(ull v, float& a, float& b) {
    asm("mov.b64 {%0,%1}, %2;" : "=f"(a), "=f"(b) : "l"(v));
}
__device__ __forceinline__ ull addx2(ull a, ull b) {
    ull r; asm("add.rn.f32x2 %0, %1, %2;" : "=l"(r) : "l"(a), "l"(b)); return r;
}
__device__ __forceinline__ ull mulx2(ull a, ull b) {
    ull r; asm("mul.rn.f32x2 %0, %1, %2;" : "=l"(r) : "l"(a), "l"(b)); return r;
}
__device__ __forceinline__ unsigned su32(const void* p) {
    unsigned r;
    asm("{.reg .u64 t; cvta.to.shared.u64 t, %1; cvt.u32.u64 %0, t;}" : "=r"(r) : "l"(p));
    return r;
}

// ---------------------------------------------------------------------------
// FPS: 8-CTA cluster per batch, 256 threads/CTA (R14 topology, tag-spin,
// single-release producer). SINGLE CHANGE vs R14 (860.6us): the per-thread
// local argmax is a left-biased compare-select tree (depth 4) producing the
// identical (max dist, smallest index on tie) pair, replacing the fmaxf tree
// + 16-deep serialized first-match select chain.
// ---------------------------------------------------------------------------
__global__ void __cluster_dims__(CSZ, 1, 1) __launch_bounds__(T, 1)
fps_kernel(const float* __restrict__ xyz,
           float* __restrict__ out_xyz,
           float* __restrict__ out_idxf)
{
    extern __shared__ float smem[];
    float*    sx   = smem;                        // winner-coord lookup copies
    float*    sy   = smem + NL;
    float*    sz   = smem + 2 * NL;
    unsigned* mb   = (unsigned*)(smem + 3 * NL);  // [2][CSZ] slots of 6 u32
    unsigned* swdi = mb + 2 * CSZ * 6;            // per-warp {distbits, idx} v2

    const int rank = blockIdx.x;
    const int b    = blockIdx.y;
    const int tid  = threadIdx.x;
    const int lane = tid & 31;
    const int warp = tid >> 5;
    const int base = rank * NL;
    const float* __restrict__ p = xyz + (size_t)b * NPTS * 3;

    // ---- one-time: load my 16 points -> packed registers + smem lookup copy
    ull x2[NPAIR], y2[NPAIR], z2[NPAIR];
    {
        float buf[48];
        const float4* p4 = (const float4*)(p + (size_t)(base + tid * PPT) * 3);
#pragma unroll
        for (int k = 0; k < 12; k++) ((float4*)buf)[k] = p4[k];
#pragma unroll
        for (int i = 0; i < PPT; i++) {
            sx[tid * PPT + i] = buf[3 * i];
            sy[tid * PPT + i] = buf[3 * i + 1];
            sz[tid * PPT + i] = buf[3 * i + 2];
        }
#pragma unroll
        for (int q = 0; q < NPAIR; q++) {
            x2[q] = pk(buf[6 * q + 0], buf[6 * q + 3]);
            y2[q] = pk(buf[6 * q + 1], buf[6 * q + 4]);
            z2[q] = pk(buf[6 * q + 2], buf[6 * q + 5]);
        }
    }

    // ---- init mailbox tags (word 5 of each slot), then one cluster barrier
    if (tid < 2 * CSZ) mb[tid * 6 + 5] = 0xFFFFFFFFu;
    __syncthreads();
    asm volatile("barrier.cluster.arrive.aligned;\n" ::: "memory");
    asm volatile("barrier.cluster.wait.aligned;\n"   ::: "memory");

    const unsigned mb_u   = su32(mb);
    const unsigned swdi_u = su32(swdi);

    // Remote slot addresses: warp0 lane r pushes into peer r's slot[parity][rank].
    unsigned rem0 = 0, rem1 = 0;
    if (warp == 0 && lane < CSZ) {
        const unsigned l0 = mb_u + (unsigned)((0 * CSZ + rank) * SLOTB);
        const unsigned l1 = mb_u + (unsigned)((1 * CSZ + rank) * SLOTB);
        asm("mapa.shared::cluster.u32 %0, %1, %2;" : "=r"(rem0) : "r"(l0), "r"(lane));
        asm("mapa.shared::cluster.u32 %0, %1, %2;" : "=r"(rem1) : "r"(l1), "r"(lane));
    }

    float dist[PPT];
#pragma unroll
    for (int i = 0; i < PPT; i++) dist[i] = 1e10f;

    int   cur = 0;
    float cx = __ldg(p + 0), cy = __ldg(p + 1), cz = __ldg(p + 2);

    for (int s = 0; s < NSAMP; s++) {
        // Output writes on a non-critical warp (warp1), state from prev iter.
        if (rank == 0 && warp == 1 && lane == 0) {
            g_idx[b * NSAMP + s]    = cur;
            out_idxf[b * NSAMP + s] = (float)cur;
            float* o = out_xyz + ((size_t)b * NSAMP + s) * 3;
            o[0] = cx; o[1] = cy; o[2] = cz;
        }

        // ---- scan: packed (dx*dx+dy*dy)+dz*dz, rn ordering (bit-match XLA)
        const ull ncx2 = pk(-cx, -cx), ncy2 = pk(-cy, -cy), ncz2 = pk(-cz, -cz);
#pragma unroll
        for (int q = 0; q < NPAIR; q++) {
            const ull dx2 = addx2(x2[q], ncx2);
            const ull dy2 = addx2(y2[q], ncy2);
            const ull dz2 = addx2(z2[q], ncz2);
            const ull d2  = addx2(addx2(mulx2(dx2, dx2), mulx2(dy2, dy2)),
                                  mulx2(dz2, dz2));
            float d0, d1; upk(d2, d0, d1);
            dist[2 * q]     = fminf(dist[2 * q],     d0);
            dist[2 * q + 1] = fminf(dist[2 * q + 1], d1);
        }

        // ---- local argmax: left-biased compare-select tree (depth 4).
        //      Strict '>' keeps the left (smaller-index) element on ties =>
        //      identical (max, first-match index) semantics, 1/5 the depth.
        float td[PPT]; int ti[PPT];
#pragma unroll
        for (int i = 0; i < PPT; i++) { td[i] = dist[i]; ti[i] = i; }
#pragma unroll
        for (int st = 1; st < PPT; st <<= 1) {
#pragma unroll
            for (int i = 0; i < PPT; i += 2 * st) {
                if (td[i + st] > td[i]) { td[i] = td[i + st]; ti[i] = ti[i + st]; }
            }
        }
        const float    bd = td[0];
        const unsigned bi = (unsigned)(base + tid * PPT + ti[0]);

        // ---- warp reduce via redux (dist>=0 => bits monotone; tie -> min idx)
        const unsigned bdb  = __float_as_uint(bd);
        const unsigned wmax = __reduce_max_sync(0xffffffffu, bdb);
        const unsigned wcnd = (bdb == wmax) ? bi : 0x7fffffffu;
        const unsigned wbi  = __reduce_min_sync(0xffffffffu, wcnd);
        if (lane == 0)
            asm volatile("st.shared.v2.b32 [%0], {%1,%2};"
                         :: "r"(swdi_u + (unsigned)(warp * 8)), "r"(wmax), "r"(wbi)
                         : "memory");
        __syncthreads();

        // ---- warp0: CTA reduce (8 warp results) + DSMEM push ----
        if (warp == 0) {
            unsigned v = 0, i = 0x7fffffffu;
            if (lane < NWARP)
                asm volatile("ld.shared.v2.b32 {%0,%1}, [%2];"
                             : "=r"(v), "=r"(i)
                             : "r"(swdi_u + (unsigned)(lane * 8)) : "memory");
            const unsigned cmax = __reduce_max_sync(0xffffffffu, v);
            const unsigned ccnd = (v == cmax) ? i : 0x7fffffffu;
            const unsigned ri   = __reduce_min_sync(0xffffffffu, ccnd);
            const int lj = (int)ri - base;                 // uniform -> LDS broadcast
            const unsigned wx = __float_as_uint(sx[lj]);
            const unsigned wy = __float_as_uint(sy[lj]);
            const unsigned wz = __float_as_uint(sz[lj]);
            if (lane < CSZ) {
                const unsigned rem = (s & 1) ? rem1 : rem0;
                asm volatile("st.shared::cluster.v2.b32 [%0], {%1,%2};"
                             :: "r"(rem), "r"(cmax), "r"(ri) : "memory");
                asm volatile("st.shared::cluster.v2.b32 [%0], {%1,%2};"
                             :: "r"(rem + 8u), "r"(wx), "r"(wy) : "memory");
                asm volatile("st.release.cluster.shared::cluster.v2.b32 [%0], {%1,%2};"
                             :: "r"(rem + 16u), "r"(wz), "r"((unsigned)s) : "memory");
            }
        }

        // ---- every warp: spin on {z,tag}; z rides the spin word ----
        const unsigned slot_a = mb_u + (unsigned)(((s & 1) * CSZ + lane) * SLOTB);
        unsigned rz = 0;
        int ok;
        do {
            unsigned tg = (unsigned)s, z_ = 0;
            if (lane < CSZ)
                asm volatile("ld.acquire.cluster.shared::cta.v2.b32 {%0,%1}, [%2];"
                             : "=r"(z_), "=r"(tg) : "r"(slot_a + 16u) : "memory");
            ok = __all_sync(0xffffffffu, tg == (unsigned)s);
            rz = z_;
        } while (!ok);

        unsigned db = 0, ridx = 0x7fffffffu;
        if (lane < CSZ)
            asm volatile("ld.shared.v2.b32 {%0,%1}, [%2];"
                         : "=r"(db), "=r"(ridx) : "r"(slot_a) : "memory");
        const unsigned gmax = __reduce_max_sync(0xffffffffu, db);
        const unsigned gcnd = (lane < CSZ && db == gmax) ? ridx : 0x7fffffffu;
        const unsigned wi   = __reduce_min_sync(0xffffffffu, gcnd);
        const int      wr   = (int)(wi >> 12);             // winner rank == lane
        // winner z via shfl; winner {x,y} via one broadcast v2 LDS
        cz = __uint_as_float(__shfl_sync(0xffffffffu, rz, wr));
        const unsigned wslot = mb_u + (unsigned)(((s & 1) * CSZ + wr) * SLOTB);
        unsigned bx, by;
        asm volatile("ld.shared.v2.b32 {%0,%1}, [%2];"
                     : "=r"(bx), "=r"(by) : "r"(wslot + 8u) : "memory");
        cur = (int)wi;
        cx = __uint_as_float(bx); cy = __uint_as_float(by);
    }
}

// ---------------------------------------------------------------------------
// Feature gather: out_fea[b][c][s] = fea[b][c][g_idx[b][s]]
// ---------------------------------------------------------------------------
__global__ void gather_kernel(const float* __restrict__ fea,
                              float* __restrict__ out_fea)
{
    const int t = blockIdx.x * blockDim.x + threadIdx.x;
    if (t >= BATCH * NCH * NSAMP) return;
    const int s = t % NSAMP;
    const int c = (t / NSAMP) % NCH;
    const int b = t / (NCH * NSAMP);
    const int id = g_idx[b * NSAMP + s];
    out_fea[t] = __ldg(fea + ((size_t)b * NCH + c) * NPTS + id);
}

extern "C" void kernel_launch(void* const* d_in, const int* in_sizes, int n_in,
                              void* d_out, int out_size)
{
    const float* xyz = (const float*)d_in[0];   // (B, N, 3)
    const float* fea = (const float*)d_in[1];   // (B, C, N)

    float* out = (float*)d_out;
    // Output layout: new_xyz (B,S,3) | new_fea (B,C,S) | indices-as-float (B,S)
    float* out_xyz  = out;
    float* out_fea  = out + (size_t)BATCH * NSAMP * 3;
    float* out_idxf = out + (size_t)BATCH * NSAMP * 3 + (size_t)BATCH * NCH * NSAMP;

    const int smem_bytes = 3 * NL * 4            // coord lookup copies
                         + 2 * CSZ * SLOTB       // mailbox slots
                         + NWARP * 8;            // per-warp {d,idx} v2 scratch
    cudaFuncSetAttribute(fps_kernel, cudaFuncAttributeMaxDynamicSharedMemorySize, smem_bytes);

    fps_kernel<<<dim3(CSZ, BATCH), T, smem_bytes>>>(xyz, out_xyz, out_idxf);

    const int total = BATCH * NCH * NSAMP;
    gather_kernel<<<(total + 255) / 256, 256>>>(fea, out_fea);
}